// round 1
// baseline (speedup 1.0000x reference)
#include <cuda_runtime.h>
#include <cstdint>

// LightGCN_75900662055226 — baseline
// N = 150000 nodes, D = 64, E = 2,000,000 edges, 3 layers, fp32.
// out[N*64] = (emb + x1 + x2 + x3) / 4 where x_{k+1}[dst] += w[e] * x_k[src].

#define NUM_USERS 100000
#define NUM_ITEMS 50000
#define NN (NUM_USERS + NUM_ITEMS)   // 150000
#define EE 2000000
#define DD 64
#define NL 3

// Scratch (static __device__ globals — no allocations allowed in kernel_launch)
__device__ float g_dinv[NN];             // degree, then dinv (in place)
__device__ float g_w[EE];                // per-edge weight
__device__ float g_x[2][NN * DD];        // ping-pong layer buffers

// ---------------------------------------------------------------------------

__global__ void k_zero_deg() {
    int i = blockIdx.x * blockDim.x + threadIdx.x;
    if (i < NN) g_dinv[i] = 0.0f;
}

__global__ void k_deg(const int* __restrict__ dst) {
    int e = blockIdx.x * blockDim.x + threadIdx.x;
    if (e < EE) atomicAdd(&g_dinv[dst[e]], 1.0f);
}

__global__ void k_dinv() {
    int i = blockIdx.x * blockDim.x + threadIdx.x;
    if (i < NN) {
        float d = g_dinv[i];
        g_dinv[i] = (d > 0.0f) ? rsqrtf(d) : 0.0f;
    }
}

__global__ void k_w(const int* __restrict__ src, const int* __restrict__ dst) {
    int e = blockIdx.x * blockDim.x + threadIdx.x;
    if (e < EE) g_w[e] = g_dinv[src[e]] * g_dinv[dst[e]];
}

// x0 = emb, out = emb (acc starts at emb). Vectorized float4.
__global__ void k_init(const float4* __restrict__ emb, float4* __restrict__ out) {
    int i = blockIdx.x * blockDim.x + threadIdx.x;
    const int n4 = NN * DD / 4;
    if (i < n4) {
        float4 v = emb[i];
        reinterpret_cast<float4*>(g_x[0])[i] = v;
        out[i] = v;
    }
}

// Zero the next-layer buffer.
__global__ void k_zero_x(int nxt) {
    int i = blockIdx.x * blockDim.x + threadIdx.x;
    const int n4 = NN * DD / 4;
    if (i < n4) {
        reinterpret_cast<float4*>(g_x[nxt])[i] = make_float4(0.f, 0.f, 0.f, 0.f);
    }
}

// Scatter: 16 threads per edge, 4 floats (one float4 gather) per thread.
// idx layout: e = idx >> 4, d = (idx & 15) * 4 — 16 consecutive threads cover
// one edge's 64-float row (coalesced within the row on both load and atomic).
__global__ void k_scatter(const int* __restrict__ src,
                          const int* __restrict__ dst,
                          int cur) {
    long long idx = (long long)blockIdx.x * blockDim.x + threadIdx.x;
    int e = (int)(idx >> 4);
    if (e >= EE) return;
    int d = ((int)idx & 15) << 2;

    int s = src[e];
    int t = dst[e];
    float w = g_w[e];
    if (w == 0.0f) return;

    const float* xin = g_x[cur];
    float* xout = g_x[cur ^ 1];

    float4 v = *reinterpret_cast<const float4*>(&xin[(long long)s * DD + d]);
    float* o = &xout[(long long)t * DD + d];
    atomicAdd(o + 0, v.x * w);
    atomicAdd(o + 1, v.y * w);
    atomicAdd(o + 2, v.z * w);
    atomicAdd(o + 3, v.w * w);
}

// out += x[nxt]   (intermediate layers)
__global__ void k_acc(float4* __restrict__ out, int nxt) {
    int i = blockIdx.x * blockDim.x + threadIdx.x;
    const int n4 = NN * DD / 4;
    if (i < n4) {
        float4 a = out[i];
        float4 b = reinterpret_cast<const float4*>(g_x[nxt])[i];
        a.x += b.x; a.y += b.y; a.z += b.z; a.w += b.w;
        out[i] = a;
    }
}

// out = (out + x[nxt]) * 0.25f   (final layer fused with the average)
__global__ void k_fin(float4* __restrict__ out, int nxt) {
    int i = blockIdx.x * blockDim.x + threadIdx.x;
    const int n4 = NN * DD / 4;
    if (i < n4) {
        float4 a = out[i];
        float4 b = reinterpret_cast<const float4*>(g_x[nxt])[i];
        a.x = (a.x + b.x) * 0.25f;
        a.y = (a.y + b.y) * 0.25f;
        a.z = (a.z + b.z) * 0.25f;
        a.w = (a.w + b.w) * 0.25f;
        out[i] = a;
    }
}

// ---------------------------------------------------------------------------

extern "C" void kernel_launch(void* const* d_in, const int* in_sizes, int n_in,
                              void* d_out, int out_size) {
    const int* edge = (const int*)d_in[0];      // [2, E] row-major
    const int* src = edge;
    const int* dst = edge + EE;
    const float* emb = (const float*)d_in[1];   // [N, 64]
    float* out = (float*)d_out;                 // [N, 64]

    const int T = 256;
    const int n4 = NN * DD / 4;

    k_zero_deg<<<(NN + T - 1) / T, T>>>();
    k_deg<<<(EE + T - 1) / T, T>>>(dst);
    k_dinv<<<(NN + T - 1) / T, T>>>();
    k_w<<<(EE + T - 1) / T, T>>>(src, dst);
    k_init<<<(n4 + T - 1) / T, T>>>((const float4*)emb, (float4*)out);

    long long scatter_threads = (long long)EE * 16;
    int scatter_blocks = (int)((scatter_threads + T - 1) / T);

    for (int l = 0; l < NL; ++l) {
        int cur = l & 1;
        int nxt = cur ^ 1;
        k_zero_x<<<(n4 + T - 1) / T, T>>>(nxt);
        k_scatter<<<scatter_blocks, T>>>(src, dst, cur);
        if (l < NL - 1)
            k_acc<<<(n4 + T - 1) / T, T>>>((float4*)out, nxt);
        else
            k_fin<<<(n4 + T - 1) / T, T>>>((float4*)out, nxt);
    }
    (void)in_sizes; (void)n_in; (void)out_size;
}

// round 2
// speedup vs baseline: 1.5746x; 1.5746x over previous
#include <cuda_runtime.h>
#include <cstdint>

// LightGCN_75900662055226 — R2: vectorized red.global.add.v4.f32 scatter
// N = 150000 nodes, D = 64, E = 2,000,000 edges, 3 layers, fp32.

#define NUM_USERS 100000
#define NUM_ITEMS 50000
#define NN (NUM_USERS + NUM_ITEMS)   // 150000
#define EE 2000000
#define DD 64
#define NL 3

__device__ float g_dinv[NN];             // degree, then dinv (in place)
__device__ float g_w[EE];                // per-edge weight
__device__ float g_x[2][NN * DD];        // ping-pong layer buffers

// ---------------------------------------------------------------------------

__global__ void k_zero_deg() {
    int i = blockIdx.x * blockDim.x + threadIdx.x;
    if (i < NN) g_dinv[i] = 0.0f;
}

__global__ void k_deg(const int* __restrict__ dst) {
    int e = blockIdx.x * blockDim.x + threadIdx.x;
    if (e < EE) atomicAdd(&g_dinv[dst[e]], 1.0f);
}

__global__ void k_dinv() {
    int i = blockIdx.x * blockDim.x + threadIdx.x;
    if (i < NN) {
        float d = g_dinv[i];
        g_dinv[i] = (d > 0.0f) ? rsqrtf(d) : 0.0f;
    }
}

__global__ void k_w(const int* __restrict__ src, const int* __restrict__ dst) {
    int e = blockIdx.x * blockDim.x + threadIdx.x;
    if (e < EE) g_w[e] = g_dinv[src[e]] * g_dinv[dst[e]];
}

// x0 = emb, out = emb (acc starts at emb).
__global__ void k_init(const float4* __restrict__ emb, float4* __restrict__ out) {
    int i = blockIdx.x * blockDim.x + threadIdx.x;
    const int n4 = NN * DD / 4;
    if (i < n4) {
        float4 v = emb[i];
        reinterpret_cast<float4*>(g_x[0])[i] = v;
        out[i] = v;
    }
}

__global__ void k_zero_x(int nxt) {
    int i = blockIdx.x * blockDim.x + threadIdx.x;
    const int n4 = NN * DD / 4;
    if (i < n4) {
        reinterpret_cast<float4*>(g_x[nxt])[i] = make_float4(0.f, 0.f, 0.f, 0.f);
    }
}

// Scatter: 16 threads per edge; each thread does ONE float4 gather and ONE
// red.global.add.v4.f32 (4x fewer atomic instructions than scalar RED).
__global__ void k_scatter(const int* __restrict__ src,
                          const int* __restrict__ dst,
                          int cur) {
    long long idx = (long long)blockIdx.x * blockDim.x + threadIdx.x;
    int e = (int)(idx >> 4);
    if (e >= EE) return;
    int d = ((int)idx & 15) << 2;

    int s = src[e];
    int t = dst[e];
    float w = g_w[e];
    if (w == 0.0f) return;

    const float* xin = g_x[cur];
    float* xout = g_x[cur ^ 1];

    float4 v = *reinterpret_cast<const float4*>(&xin[(long long)s * DD + d]);
    v.x *= w; v.y *= w; v.z *= w; v.w *= w;

    float* o = &xout[(long long)t * DD + d];
    asm volatile("red.global.add.v4.f32 [%0], {%1, %2, %3, %4};"
                 :: "l"(o), "f"(v.x), "f"(v.y), "f"(v.z), "f"(v.w)
                 : "memory");
}

// out += x[nxt]
__global__ void k_acc(float4* __restrict__ out, int nxt) {
    int i = blockIdx.x * blockDim.x + threadIdx.x;
    const int n4 = NN * DD / 4;
    if (i < n4) {
        float4 a = out[i];
        float4 b = reinterpret_cast<const float4*>(g_x[nxt])[i];
        a.x += b.x; a.y += b.y; a.z += b.z; a.w += b.w;
        out[i] = a;
    }
}

// out = (out + x[nxt]) * 0.25f
__global__ void k_fin(float4* __restrict__ out, int nxt) {
    int i = blockIdx.x * blockDim.x + threadIdx.x;
    const int n4 = NN * DD / 4;
    if (i < n4) {
        float4 a = out[i];
        float4 b = reinterpret_cast<const float4*>(g_x[nxt])[i];
        a.x = (a.x + b.x) * 0.25f;
        a.y = (a.y + b.y) * 0.25f;
        a.z = (a.z + b.z) * 0.25f;
        a.w = (a.w + b.w) * 0.25f;
        out[i] = a;
    }
}

// ---------------------------------------------------------------------------

extern "C" void kernel_launch(void* const* d_in, const int* in_sizes, int n_in,
                              void* d_out, int out_size) {
    const int* edge = (const int*)d_in[0];      // [2, E] row-major
    const int* src = edge;
    const int* dst = edge + EE;
    const float* emb = (const float*)d_in[1];   // [N, 64]
    float* out = (float*)d_out;                 // [N, 64]

    const int T = 256;
    const int n4 = NN * DD / 4;

    k_zero_deg<<<(NN + T - 1) / T, T>>>();
    k_deg<<<(EE + T - 1) / T, T>>>(dst);
    k_dinv<<<(NN + T - 1) / T, T>>>();
    k_w<<<(EE + T - 1) / T, T>>>(src, dst);
    k_init<<<(n4 + T - 1) / T, T>>>((const float4*)emb, (float4*)out);

    long long scatter_threads = (long long)EE * 16;
    int scatter_blocks = (int)((scatter_threads + T - 1) / T);

    for (int l = 0; l < NL; ++l) {
        int cur = l & 1;
        int nxt = cur ^ 1;
        k_zero_x<<<(n4 + T - 1) / T, T>>>(nxt);
        k_scatter<<<scatter_blocks, T>>>(src, dst, cur);
        if (l < NL - 1)
            k_acc<<<(n4 + T - 1) / T, T>>>((float4*)out, nxt);
        else
            k_fin<<<(n4 + T - 1) / T, T>>>((float4*)out, nxt);
    }
    (void)in_sizes; (void)n_in; (void)out_size;
}

// round 3
// speedup vs baseline: 3.2131x; 2.0406x over previous
#include <cuda_runtime.h>
#include <cstdint>

// LightGCN_75900662055226 — R3: CSR-by-dst counting sort + pull-mode SpMM
// (no float atomics in the propagation layers; fused accumulate/average).

#define NUM_USERS 100000
#define NUM_ITEMS 50000
#define NN (NUM_USERS + NUM_ITEMS)   // 150000
#define EE 2000000
#define DD 64
#define NL 3

#define NB ((NN + 255) / 256)        // 586 scan blocks

__device__ int   g_ideg[NN];         // integer in-degree
__device__ float g_dinv[NN];         // 1/sqrt(deg)
__device__ int   g_bsum[NB];         // per-block degree sums
__device__ int   g_boff[NB];         // exclusive scan of block sums
__device__ int   g_rowptr[NN + 1];   // CSR row pointers (by dst)
__device__ int   g_fill[NN];         // fill cursors for binning
__device__ int2  g_csr[EE];          // (src, w-as-int-bits) sorted by dst
__device__ float g_x[2][NN * DD];    // ping-pong layer buffers

// ---------------------------------------------------------------------------

__global__ void k_zero_deg() {
    int i = blockIdx.x * blockDim.x + threadIdx.x;
    if (i < NN) g_ideg[i] = 0;
}

__global__ void k_deg(const int* __restrict__ dst) {
    int e = blockIdx.x * blockDim.x + threadIdx.x;
    if (e < EE) atomicAdd(&g_ideg[dst[e]], 1);
}

__global__ void k_dinv() {
    int i = blockIdx.x * blockDim.x + threadIdx.x;
    if (i < NN) {
        int d = g_ideg[i];
        g_dinv[i] = (d > 0) ? rsqrtf((float)d) : 0.0f;
    }
}

// --- 3-step exclusive scan of g_ideg -> g_rowptr ---------------------------

__global__ void k_scan1() {                       // per-block reduce
    __shared__ int sh[256];
    int i = blockIdx.x * 256 + threadIdx.x;
    int v = (i < NN) ? g_ideg[i] : 0;
    sh[threadIdx.x] = v;
    __syncthreads();
    for (int s = 128; s > 0; s >>= 1) {
        if (threadIdx.x < s) sh[threadIdx.x] += sh[threadIdx.x + s];
        __syncthreads();
    }
    if (threadIdx.x == 0) g_bsum[blockIdx.x] = sh[0];
}

__global__ void k_scan2() {                       // single-block scan of block sums
    __shared__ int sh[1024];
    int i = threadIdx.x;
    int v = (i < NB) ? g_bsum[i] : 0;
    sh[i] = v;
    __syncthreads();
    for (int s = 1; s < 1024; s <<= 1) {          // inclusive Hillis-Steele
        int t = (i >= s) ? sh[i - s] : 0;
        __syncthreads();
        sh[i] += t;
        __syncthreads();
    }
    if (i < NB) g_boff[i] = sh[i] - v;            // exclusive
}

__global__ void k_scan3() {                       // per-block exclusive scan + offset
    __shared__ int sh[256];
    int i = blockIdx.x * 256 + threadIdx.x;
    int v = (i < NN) ? g_ideg[i] : 0;
    sh[threadIdx.x] = v;
    __syncthreads();
    for (int s = 1; s < 256; s <<= 1) {           // inclusive
        int t = (threadIdx.x >= s) ? sh[threadIdx.x - s] : 0;
        __syncthreads();
        sh[threadIdx.x] += t;
        __syncthreads();
    }
    if (i < NN) {
        int start = g_boff[blockIdx.x] + sh[threadIdx.x] - v;  // exclusive
        g_rowptr[i] = start;
        g_fill[i] = start;
    }
    if (i == 0) g_rowptr[NN] = EE;
}

// --- bin edges into CSR (by dst), weight precomputed ------------------------

__global__ void k_fill(const int* __restrict__ src, const int* __restrict__ dst) {
    int e = blockIdx.x * blockDim.x + threadIdx.x;
    if (e >= EE) return;
    int s = src[e];
    int t = dst[e];
    float w = g_dinv[s] * g_dinv[t];
    int pos = atomicAdd(&g_fill[t], 1);
    g_csr[pos] = make_int2(s, __float_as_int(w));
}

// --- x0 = emb, out = emb ----------------------------------------------------

__global__ void k_init(const float4* __restrict__ emb, float4* __restrict__ out) {
    int i = blockIdx.x * blockDim.x + threadIdx.x;
    const int n4 = NN * DD / 4;
    if (i < n4) {
        float4 v = emb[i];
        reinterpret_cast<float4*>(g_x[0])[i] = v;
        out[i] = v;
    }
}

// --- pull-mode SpMM: one warp per dst row, lane owns one float2 column -----
// mode 0: out += acc (intermediate layers); mode 1: out = (out + acc) * 0.25
__global__ void k_pull(int cur, int mode, float2* __restrict__ out) {
    int row = (blockIdx.x * blockDim.x + threadIdx.x) >> 5;
    int lane = threadIdx.x & 31;
    if (row >= NN) return;

    int beg = g_rowptr[row];
    int end = g_rowptr[row + 1];

    const float2* __restrict__ xin = (const float2*)g_x[cur];
    float2 acc = make_float2(0.0f, 0.0f);

    for (int base = beg; base < end; base += 32) {
        int e = base + lane;
        int2 meta = (e < end) ? g_csr[e] : make_int2(0, 0);
        int cnt = min(32, end - base);
        for (int j = 0; j < cnt; ++j) {
            int   sj = __shfl_sync(0xffffffffu, meta.x, j);
            float wj = __int_as_float(__shfl_sync(0xffffffffu, meta.y, j));
            float2 v = xin[sj * 32 + lane];
            acc.x += wj * v.x;
            acc.y += wj * v.y;
        }
    }

    int oidx = row * 32 + lane;
    ((float2*)g_x[cur ^ 1])[oidx] = acc;

    float2 o = out[oidx];
    if (mode == 0) {
        o.x += acc.x; o.y += acc.y;
    } else {
        o.x = (o.x + acc.x) * 0.25f;
        o.y = (o.y + acc.y) * 0.25f;
    }
    out[oidx] = o;
}

// ---------------------------------------------------------------------------

extern "C" void kernel_launch(void* const* d_in, const int* in_sizes, int n_in,
                              void* d_out, int out_size) {
    const int* edge = (const int*)d_in[0];      // [2, E] row-major
    const int* src = edge;
    const int* dst = edge + EE;
    const float* emb = (const float*)d_in[1];   // [N, 64]
    float* out = (float*)d_out;                 // [N, 64]

    const int T = 256;
    const int n4 = NN * DD / 4;

    k_zero_deg<<<(NN + T - 1) / T, T>>>();
    k_deg<<<(EE + T - 1) / T, T>>>(dst);
    k_dinv<<<(NN + T - 1) / T, T>>>();

    k_scan1<<<NB, 256>>>();
    k_scan2<<<1, 1024>>>();
    k_scan3<<<NB, 256>>>();

    k_fill<<<(EE + T - 1) / T, T>>>(src, dst);
    k_init<<<(n4 + T - 1) / T, T>>>((const float4*)emb, (float4*)out);

    int pull_blocks = (NN * 32 + T - 1) / T;    // one warp per row
    for (int l = 0; l < NL; ++l) {
        int cur = l & 1;
        int mode = (l == NL - 1) ? 1 : 0;
        k_pull<<<pull_blocks, T>>>(cur, mode, (float2*)out);
    }
    (void)in_sizes; (void)n_in; (void)out_size;
}